// round 13
// baseline (speedup 1.0000x reference)
#include <cuda_runtime.h>
#include <math.h>
#include <cstdint>

typedef unsigned long long ull;

// Problem constants
#define L_STEPS 128
#define NB 64
#define HID 4096            // 32*16*8
#define T1S 128             // t1 row stride (words)
#define T2R 160             // t2 row stride (xw only); (e,c) -> e*10 + c
#define L_PER 16            // timesteps per xw CTA

// XW scratch: (L, 3, N, 4096) fp32 = 402 MB.
__device__ float g_xw[(size_t)L_STEPS * 3 * NB * HID];

__device__ __forceinline__ void fma2(ull& acc, ull a, ull b) {
    asm("fma.rn.f32x2 %0, %1, %2, %0;" : "+l"(acc) : "l"(a), "l"(b));
}
__device__ __forceinline__ ull pack2(float lo, float hi) {
    ull r; asm("mov.b64 %0, {%1, %2};" : "=l"(r) : "f"(lo), "f"(hi)); return r;
}
__device__ __forceinline__ void unpack2(float& lo, float& hi, ull v) {
    asm("mov.b64 {%0, %1}, %2;" : "=f"(lo), "=f"(hi) : "l"(v));
}
__device__ __forceinline__ uint32_t smem_u32(const void* p) {
    uint32_t a;
    asm("{ .reg .u64 t; cvta.to.shared.u64 t, %1; cvt.u32.u64 %0, t; }" : "=r"(a) : "l"(p));
    return a;
}
__device__ __forceinline__ uint32_t mapa_u32(uint32_t addr, uint32_t rank) {
    uint32_t r;
    asm("mapa.shared::cluster.u32 %0, %1, %2;" : "=r"(r) : "r"(addr), "r"(rank));
    return r;
}
__device__ __forceinline__ void st_cluster_b64(uint32_t addr, ull v) {
    asm volatile("st.shared::cluster.b64 [%0], %1;" :: "r"(addr), "l"(v) : "memory");
}

// ---------------------------------------------------------------------------
// Stage 1: XW for 16 timesteps per CTA. Grid (NB, L/16), 512 threads.
// Weights stored PRE-DUPLICATED for direct f32x2 feeds (no dup2 MOVs).
// ---------------------------------------------------------------------------
__global__ __launch_bounds__(512) void xw_kernel(
    const float* __restrict__ x,
    const float* __restrict__ W1,   // (3,32,32)
    const float* __restrict__ W2,   // (3,16,16)
    const float* __restrict__ W3)   // (3,8,8)
{
    extern __shared__ float sm[];
    float* xs  = sm;              // 2 x 4096 (double buffer): x[a][b*8+c]
    float* t1  = xs + 8192;       // 96*T1S = 12288, rows r = g*32+d
    float* t2  = t1 + 12288;      // 96*T2R = 15360
    float* w1d = t2 + 15360;      // 6144: w1d[a*192 + r*2 + {0,1}] = W1[g,d,a], r=g*32+d
    float* w2d = w1d + 6144;      // 1536: w2d[g*512 + b*32 + e*2 + {0,1}] = W2[g,e,b]
    float* w3s = w2d + 1536;      // 192

    const int t  = threadIdx.x;
    const int n  = blockIdx.x;
    const int l0 = blockIdx.y * L_PER;

    for (int i = t; i < 6144; i += 512) {
        int a = i / 192, q = i % 192, r = q >> 1;
        int g = r >> 5, d = r & 31;
        w1d[i] = W1[(g * 32 + d) * 32 + a];
    }
    for (int i = t; i < 1536; i += 512) {
        int g = i >> 9, q = i & 511, b = q >> 5, e = (q & 31) >> 1;
        w2d[i] = W2[(g * 16 + e) * 16 + b];
    }
    for (int i = t; i < 192; i += 512) w3s[i] = W3[i];
    {
        const float4* xg4 = reinterpret_cast<const float4*>(x + ((size_t)n * L_STEPS + l0) * HID);
        float4* xs4 = reinterpret_cast<float4*>(xs);
        xs4[t] = xg4[t];
        xs4[t + 512] = xg4[t + 512];
    }
    __syncthreads();

    const int warp = t >> 5, lane = t & 31;
    const int r0  = warp * 8;
    const int bc0 = lane * 4;
    const int e2  = lane >> 1;
    const int c4  = (lane & 1) * 4;

    for (int ll = 0; ll < L_PER; ll++) {
        const int l = l0 + ll;
        float* cur = xs + (ll & 1) * 4096;
        float* nxt = xs + ((ll & 1) ^ 1) * 4096;

        float4 pf0, pf1;
        if (ll + 1 < L_PER) {
            const float4* xg4 = reinterpret_cast<const float4*>(
                x + ((size_t)n * L_STEPS + l + 1) * HID);
            pf0 = xg4[t];
            pf1 = xg4[t + 512];
        }

        if (warp < 12) {
            // ---- p1: t1[r][bc] = sum_a W1[r,a] * x[a][bc], 8 rows/warp ----
            const float* wdp = w1d + r0 * 2;
            ull acc[8][2];
#pragma unroll
            for (int j = 0; j < 8; j++) { acc[j][0] = 0; acc[j][1] = 0; }
#pragma unroll
            for (int a = 0; a < 32; a++) {
                ulonglong2 xv  = *reinterpret_cast<const ulonglong2*>(&cur[a * 128 + bc0]);
                ulonglong2 w01 = *reinterpret_cast<const ulonglong2*>(&wdp[a * 192]);
                ulonglong2 w23 = *reinterpret_cast<const ulonglong2*>(&wdp[a * 192 + 4]);
                ulonglong2 w45 = *reinterpret_cast<const ulonglong2*>(&wdp[a * 192 + 8]);
                ulonglong2 w67 = *reinterpret_cast<const ulonglong2*>(&wdp[a * 192 + 12]);
                fma2(acc[0][0], w01.x, xv.x);  fma2(acc[0][1], w01.x, xv.y);
                fma2(acc[1][0], w01.y, xv.x);  fma2(acc[1][1], w01.y, xv.y);
                fma2(acc[2][0], w23.x, xv.x);  fma2(acc[2][1], w23.x, xv.y);
                fma2(acc[3][0], w23.y, xv.x);  fma2(acc[3][1], w23.y, xv.y);
                fma2(acc[4][0], w45.x, xv.x);  fma2(acc[4][1], w45.x, xv.y);
                fma2(acc[5][0], w45.y, xv.x);  fma2(acc[5][1], w45.y, xv.y);
                fma2(acc[6][0], w67.x, xv.x);  fma2(acc[6][1], w67.x, xv.y);
                fma2(acc[7][0], w67.y, xv.x);  fma2(acc[7][1], w67.y, xv.y);
            }
#pragma unroll
            for (int j = 0; j < 8; j++) {
                ulonglong2 st; st.x = acc[j][0]; st.y = acc[j][1];
                *reinterpret_cast<ulonglong2*>(&t1[(r0 + j) * T1S + bc0]) = st;
            }
            __syncwarp();

            // ---- p2: t2[r][e*10+c] = sum_b W2[g,e,b]*t1[r][b*8+c] ----
            const int g = warp >> 2;
            const float* w2g = w2d + g * 512;
            ull a2[8][2];
#pragma unroll
            for (int j = 0; j < 8; j++) { a2[j][0] = 0; a2[j][1] = 0; }
#pragma unroll
            for (int b = 0; b < 16; b++) {
                ull wd = *reinterpret_cast<const ull*>(&w2g[b * 32 + e2 * 2]);
#pragma unroll
                for (int j = 0; j < 8; j++) {
                    ulonglong2 tv = *reinterpret_cast<const ulonglong2*>(
                        &t1[(r0 + j) * T1S + b * 8 + c4]);
                    fma2(a2[j][0], wd, tv.x);
                    fma2(a2[j][1], wd, tv.y);
                }
            }
#pragma unroll
            for (int j = 0; j < 8; j++) {
                float* t2r = t2 + (r0 + j) * T2R + e2 * 10 + c4;
                *reinterpret_cast<ull*>(t2r)     = a2[j][0];
                *reinterpret_cast<ull*>(t2r + 2) = a2[j][1];
            }
        }
        __syncthreads();

        // ---- p3: out[(d*16+e)*8+f] = sum_c W3[g,f,c] * t2[g*32+d][e*10+c] ----
        {
            const int d = t >> 4, e = t & 15;
#pragma unroll
            for (int g = 0; g < 3; g++) {
                const float* t2c = t2 + (g * 32 + d) * T2R + e * 10;
                float col[8];
#pragma unroll
                for (int k = 0; k < 4; k++) {
                    float2 v = *reinterpret_cast<const float2*>(&t2c[k * 2]);
                    col[2 * k] = v.x;  col[2 * k + 1] = v.y;
                }
                const float* w3g = w3s + g * 64;
                float o[8];
#pragma unroll
                for (int f = 0; f < 8; f++) {
                    float4 ua = *reinterpret_cast<const float4*>(&w3g[f * 8]);
                    float4 ub = *reinterpret_cast<const float4*>(&w3g[f * 8 + 4]);
                    o[f] = ua.x * col[0] + ua.y * col[1] + ua.z * col[2] + ua.w * col[3]
                         + ub.x * col[4] + ub.y * col[5] + ub.z * col[6] + ub.w * col[7];
                }
                float* outg = g_xw + (((size_t)l * 3 + g) * NB + n) * HID + t * 8;
                *reinterpret_cast<float4*>(outg)     = make_float4(o[0], o[1], o[2], o[3]);
                *reinterpret_cast<float4*>(outg + 4) = make_float4(o[4], o[5], o[6], o[7]);
            }
        }

        if (ll + 1 < L_PER) {
            float4* nx4 = reinterpret_cast<float4*>(nxt);
            nx4[t] = pf0;
            nx4[t + 512] = pf1;
        }
        __syncthreads();
    }
}

// ---------------------------------------------------------------------------
// Stage 2: GRU recurrence. Cluster of 2 CTAs per sample (128 CTAs, 512 thr).
// CTA owns d in [rank*16, rank*16+16). Weights pre-duplicated for f32x2.
// p1: 12 warps x 4 rows. One __syncthreads. p2+p3 fused in registers across
// all 16 warps (warp = dd) with shfl-pair t2 exchange. DSMEM + cluster barrier.
// ---------------------------------------------------------------------------
__global__ __launch_bounds__(512) __cluster_dims__(2, 1, 1)
void gru_kernel(
    const float* __restrict__ U1,   // (3,32,32)
    const float* __restrict__ U2,   // (3,16,16)
    const float* __restrict__ U3,   // (3,8,8)
    float* __restrict__ out)        // outs (N,L,4096) then h_last (N,4096)
{
    extern __shared__ float sm[];
    float* h0  = sm;                 // 4096
    float* h1  = h0 + 4096;          // 4096
    float* t1  = h1 + 4096;          // 48*T1S = 6144   rows r = g*16+dd
    float* u1d = t1 + 6144;          // 3072: u1d[a*96 + r*2 + {0,1}] = U1[g, rank*16+dd, a]
    float* w2d = u1d + 3072;         // 1536: w2d[g*512 + b*32 + e*2 + {0,1}] = U2[g,e,b]
    float* u3s = w2d + 1536;         // 192

    const int t    = threadIdx.x;
    const int n    = blockIdx.x >> 1;
    const int rank = blockIdx.x & 1;
    const int peer = rank ^ 1;

    for (int i = t; i < 4096; i += 512) h0[i] = 0.f;
    for (int i = t; i < 3072; i += 512) {
        int a = i / 96, q = i % 96, r = q >> 1;
        int g = r >> 4, dd = r & 15;
        u1d[i] = U1[((g * 32) + rank * 16 + dd) * 32 + a];
    }
    for (int i = t; i < 1536; i += 512) {
        int g = i >> 9, q = i & 511, b = q >> 5, e = (q & 31) >> 1;
        w2d[i] = U2[(g * 16 + e) * 16 + b];
    }
    for (int i = t; i < 192; i += 512) u3s[i] = U3[i];
    __syncthreads();

    const uint32_t h0a = smem_u32(h0);
    const uint32_t h1a = smem_u32(h1);

    const int warp = t >> 5, lane = t & 31;
    // p1 (warps 0..11): r0 = 4 t1-rows; lane -> 4 cols
    const int r0  = warp * 4;
    const int bc0 = lane * 4;
    // p2+p3 (all warps, warp = dd): lane -> (e2, c/f-half)
    const int e2 = lane >> 1;
    const int c4 = (lane & 1) * 4;          // p2 column half
    const int f0 = c4;                      // p3 f half
    const bool loLane = ((lane & 1) == 0);
    const int gbase = ((rank * 16 + warp) * 16 + e2) * 8 + f0;  // 4 global hidden elems

    // hoisted DSMEM addresses (constant across the loop)
    const uint32_t raH1 = mapa_u32(h1a + (uint32_t)gbase * 4u, (uint32_t)peer); // hn when l even
    const uint32_t raH0 = mapa_u32(h0a + (uint32_t)gbase * 4u, (uint32_t)peer); // hn when l odd

    float* hc = h0;
    float* hn = h1;

    for (int l = 0; l < L_STEPS; l++) {
        // XW prefetch for p3 — issued first, hidden under p1
        float4 xf[3];
#pragma unroll
        for (int g = 0; g < 3; g++)
            xf[g] = *reinterpret_cast<const float4*>(
                g_xw + (((size_t)l * 3 + g) * NB + n) * HID + gbase);

        // ---- p1 (warps 0-11): t1[r][bc] = sum_a U1[r,a]*hc[a*128+bc] ----
        if (warp < 12) {
            const float* udp = u1d + r0 * 2;
            ull acc2[4][2];
#pragma unroll
            for (int j = 0; j < 4; j++) { acc2[j][0] = 0; acc2[j][1] = 0; }
#pragma unroll
            for (int a = 0; a < 32; a++) {
                ulonglong2 hv  = *reinterpret_cast<const ulonglong2*>(&hc[a * 128 + bc0]);
                ulonglong2 w01 = *reinterpret_cast<const ulonglong2*>(&udp[a * 96]);
                ulonglong2 w23 = *reinterpret_cast<const ulonglong2*>(&udp[a * 96 + 4]);
                fma2(acc2[0][0], w01.x, hv.x);  fma2(acc2[0][1], w01.x, hv.y);
                fma2(acc2[1][0], w01.y, hv.x);  fma2(acc2[1][1], w01.y, hv.y);
                fma2(acc2[2][0], w23.x, hv.x);  fma2(acc2[2][1], w23.x, hv.y);
                fma2(acc2[3][0], w23.y, hv.x);  fma2(acc2[3][1], w23.y, hv.y);
            }
#pragma unroll
            for (int j = 0; j < 4; j++) {
                ulonglong2 st; st.x = acc2[j][0]; st.y = acc2[j][1];
                *reinterpret_cast<ulonglong2*>(&t1[(r0 + j) * T1S + bc0]) = st;
            }
        }
        __syncthreads();

        // ---- p2+p3 fused (all 16 warps, warp = dd): register-only t2 ----
        float hu[3][4];
#pragma unroll
        for (int g = 0; g < 3; g++) {
            const float* t1r = t1 + (g * 16 + warp) * T1S;
            const float* w2g = w2d + g * 512;
            ull a0 = 0, a1 = 0;
#pragma unroll
            for (int b = 0; b < 16; b++) {
                ulonglong2 tv = *reinterpret_cast<const ulonglong2*>(&t1r[b * 8 + c4]);
                ull wd = *reinterpret_cast<const ull*>(&w2g[b * 32 + e2 * 2]);
                fma2(a0, wd, tv.x);      // t2[e2][c4, c4+1]
                fma2(a1, wd, tv.y);      // t2[e2][c4+2, c4+3]
            }
            // lane pair {2k, 2k+1} jointly holds t2[k][0..7]; exchange halves
            float m0, m1, m2, m3;
            unpack2(m0, m1, a0);
            unpack2(m2, m3, a1);
            float o0 = __shfl_xor_sync(0xffffffffu, m0, 1);
            float o1 = __shfl_xor_sync(0xffffffffu, m1, 1);
            float o2 = __shfl_xor_sync(0xffffffffu, m2, 1);
            float o3 = __shfl_xor_sync(0xffffffffu, m3, 1);
            float col[8];
            col[0] = loLane ? m0 : o0;  col[1] = loLane ? m1 : o1;
            col[2] = loLane ? m2 : o2;  col[3] = loLane ? m3 : o3;
            col[4] = loLane ? o0 : m0;  col[5] = loLane ? o1 : m1;
            col[6] = loLane ? o2 : m2;  col[7] = loLane ? o3 : m3;

            const float* u3g = u3s + g * 64;
#pragma unroll
            for (int j = 0; j < 4; j++) {
                float4 ua = *reinterpret_cast<const float4*>(&u3g[(f0 + j) * 8]);
                float4 ub = *reinterpret_cast<const float4*>(&u3g[(f0 + j) * 8 + 4]);
                hu[g][j] = ua.x * col[0] + ua.y * col[1] + ua.z * col[2] + ua.w * col[3]
                         + ub.x * col[4] + ub.y * col[5] + ub.z * col[6] + ub.w * col[7];
            }
        }

        // ---- gate combine for 4 elements (gbase..+3) ----
        float4 ho = *reinterpret_cast<const float4*>(&hc[gbase]);
        float hold[4] = {ho.x, ho.y, ho.z, ho.w};
        float xz[4] = {xf[0].x, xf[0].y, xf[0].z, xf[0].w};
        float xr[4] = {xf[1].x, xf[1].y, xf[1].z, xf[1].w};
        float xh[4] = {xf[2].x, xf[2].y, xf[2].z, xf[2].w};

        float res[4];
#pragma unroll
        for (int j = 0; j < 4; j++) {
            float z  = 1.f / (1.f + __expf(-(xz[j] + hu[0][j])));
            float r  = 1.f / (1.f + __expf(-(xr[j] + hu[1][j])));
            float ax = xh[j] + r * hu[2][j];
            float e2x = __expf(2.f * ax);
            float hh = 1.f - 2.f / (e2x + 1.f);      // tanh, NaN-safe
            res[j] = z * hold[j] + (1.f - z) * hh;
        }
        float4 r4 = make_float4(res[0], res[1], res[2], res[3]);
        *reinterpret_cast<float4*>(&hn[gbase]) = r4;

        // publish our half to peer's hn via DSMEM (2x b64; hoisted mapa)
        {
            uint32_t ra = (l & 1) ? raH0 : raH1;
            st_cluster_b64(ra,     pack2(res[0], res[1]));
            st_cluster_b64(ra + 8, pack2(res[2], res[3]));
        }

        // split cluster barrier; out STG hidden between arrive and wait
        asm volatile("barrier.cluster.arrive.aligned;" ::: "memory");
        *reinterpret_cast<float4*>(out + ((size_t)n * L_STEPS + l) * HID + gbase) = r4;
        asm volatile("barrier.cluster.wait.aligned;"   ::: "memory");

        float* tmp = hc; hc = hn; hn = tmp;
    }

    // h_last: each CTA writes its own half
    float* hl = out + (size_t)NB * L_STEPS * HID + (size_t)n * HID + rank * 2048;
    const float* hsrc = hc + rank * 2048;
    for (int i = t; i < 2048; i += 512) hl[i] = hsrc[i];
}

// ---------------------------------------------------------------------------
extern "C" void kernel_launch(void* const* d_in, const int* in_sizes, int n_in,
                              void* d_out, int out_size)
{
    const float* x  = (const float*)d_in[0];
    const float* W1 = (const float*)d_in[1];
    const float* W2 = (const float*)d_in[2];
    const float* W3 = (const float*)d_in[3];
    const float* U1 = (const float*)d_in[4];
    const float* U2 = (const float*)d_in[5];
    const float* U3 = (const float*)d_in[6];
    float* out = (float*)d_out;

    const int SMEM1 = (8192 + 12288 + 15360 + 6144 + 1536 + 192) * (int)sizeof(float);
    const int SMEM2 = (4096 * 2 + 6144 + 3072 + 1536 + 192) * (int)sizeof(float);

    cudaFuncSetAttribute(xw_kernel,  cudaFuncAttributeMaxDynamicSharedMemorySize, SMEM1);
    cudaFuncSetAttribute(gru_kernel, cudaFuncAttributeMaxDynamicSharedMemorySize, SMEM2);

    dim3 grid1(NB, L_STEPS / L_PER);
    xw_kernel<<<grid1, 512, SMEM1>>>(x, W1, W2, W3);
    gru_kernel<<<NB * 2, 512, SMEM2>>>(U1, U2, U3, out);
}

// round 14
// speedup vs baseline: 1.1918x; 1.1918x over previous
#include <cuda_runtime.h>
#include <math.h>
#include <cstdint>

typedef unsigned long long ull;

// Problem constants
#define L_STEPS 128
#define NB 64
#define HID 4096            // 32*16*8
#define T1S 128             // t1 row stride (words)
#define L_PER 16            // timesteps per xw CTA

// XW scratch: (L, 3, N, 4096) fp32 = 402 MB.
__device__ float g_xw[(size_t)L_STEPS * 3 * NB * HID];

__device__ __forceinline__ void fma2(ull& acc, ull a, ull b) {
    asm("fma.rn.f32x2 %0, %1, %2, %0;" : "+l"(acc) : "l"(a), "l"(b));
}
__device__ __forceinline__ ull dup2(float x) {
    ull r; asm("mov.b64 %0, {%1, %1};" : "=l"(r) : "f"(x)); return r;
}
__device__ __forceinline__ ull pack2(float lo, float hi) {
    ull r; asm("mov.b64 %0, {%1, %2};" : "=l"(r) : "f"(lo), "f"(hi)); return r;
}
__device__ __forceinline__ void unpack2(float& lo, float& hi, ull v) {
    asm("mov.b64 {%0, %1}, %2;" : "=f"(lo), "=f"(hi) : "l"(v));
}
__device__ __forceinline__ uint32_t smem_u32(const void* p) {
    uint32_t a;
    asm("{ .reg .u64 t; cvta.to.shared.u64 t, %1; cvt.u32.u64 %0, t; }" : "=r"(a) : "l"(p));
    return a;
}
__device__ __forceinline__ uint32_t mapa_u32(uint32_t addr, uint32_t rank) {
    uint32_t r;
    asm("mapa.shared::cluster.u32 %0, %1, %2;" : "=r"(r) : "r"(addr), "r"(rank));
    return r;
}
__device__ __forceinline__ void st_cluster_b64(uint32_t addr, ull v) {
    asm volatile("st.shared::cluster.b64 [%0], %1;" :: "r"(addr), "l"(v) : "memory");
}

// ---------------------------------------------------------------------------
// Stage 1: XW for 16 timesteps per CTA. Grid (NB, L/16), 512 threads.
// Warp-local p1 -> p2 -> p3 per warp (warp w owns rows 8w..8w+7; t2 lives in
// registers via lane-pair shuffle; no t2 SMEM, no p2/p3 barrier). Warps 12-15
// copy x[l+1] GMEM->SMEM during p1. 98 KB SMEM -> 2 CTAs/SM.
// ---------------------------------------------------------------------------
__global__ __launch_bounds__(512) void xw_kernel(
    const float* __restrict__ x,
    const float* __restrict__ W1,   // (3,32,32)
    const float* __restrict__ W2,   // (3,16,16)
    const float* __restrict__ W3)   // (3,8,8)
{
    extern __shared__ float sm[];
    float* xs  = sm;              // 2 x 4096 (double buffer): x[a][b*8+c]
    float* t1  = xs + 8192;       // 96*T1S = 12288, rows r = g*32+d
    float* w1t = t1 + 12288;      // 3072: w1t[a*96 + g*32 + d] = W1[g,d,a]
    float* w2t = w1t + 3072;      // 768:  w2t[g*256 + b*16 + e] = W2[g,e,b]
    float* w3s = w2t + 768;       // 192

    const int t  = threadIdx.x;
    const int n  = blockIdx.x;
    const int l0 = blockIdx.y * L_PER;

    for (int i = t; i < 3072; i += 512) {
        int g = i >> 10, rem = i & 1023, d = rem >> 5, a = rem & 31;
        w1t[a * 96 + g * 32 + d] = W1[i];
    }
    for (int i = t; i < 768; i += 512) {
        int g = i >> 8, rem = i & 255, e = rem >> 4, b = rem & 15;
        w2t[g * 256 + b * 16 + e] = W2[i];
    }
    for (int i = t; i < 192; i += 512) w3s[i] = W3[i];
    {
        const float4* xg4 = reinterpret_cast<const float4*>(x + ((size_t)n * L_STEPS + l0) * HID);
        float4* xs4 = reinterpret_cast<float4*>(xs);
        xs4[t] = xg4[t];
        xs4[t + 512] = xg4[t + 512];
    }
    __syncthreads();

    const int warp = t >> 5, lane = t & 31;
    const int r0  = warp * 8;               // 8 rows per warp (warps 0..11)
    const int bc0 = lane * 4;               // p1: 4 cols per lane
    const int e2  = lane >> 1;              // p2/p3: e
    const int c4  = (lane & 1) * 4;         // p2 column half
    const int f0  = c4;                     // p3 f half
    const bool loLane = ((lane & 1) == 0);

    for (int ll = 0; ll < L_PER; ll++) {
        const int l = l0 + ll;
        float* cur = xs + (ll & 1) * 4096;
        float* nxt = xs + ((ll & 1) ^ 1) * 4096;

        if (warp < 12) {
            // ---- p1: t1[r][bc] = sum_a W1t[a][r] * x[a][bc], 8 rows ----
            ull acc[8][2];
#pragma unroll
            for (int j = 0; j < 8; j++) { acc[j][0] = 0; acc[j][1] = 0; }
#pragma unroll
            for (int a = 0; a < 32; a++) {
                ulonglong2 xv = *reinterpret_cast<const ulonglong2*>(&cur[a * 128 + bc0]);
                float4 wa = *reinterpret_cast<const float4*>(&w1t[a * 96 + r0]);
                float4 wb = *reinterpret_cast<const float4*>(&w1t[a * 96 + r0 + 4]);
                ull w0 = dup2(wa.x), w1 = dup2(wa.y), w2 = dup2(wa.z), w3 = dup2(wa.w);
                ull w4 = dup2(wb.x), w5 = dup2(wb.y), w6 = dup2(wb.z), w7 = dup2(wb.w);
                fma2(acc[0][0], w0, xv.x);  fma2(acc[0][1], w0, xv.y);
                fma2(acc[1][0], w1, xv.x);  fma2(acc[1][1], w1, xv.y);
                fma2(acc[2][0], w2, xv.x);  fma2(acc[2][1], w2, xv.y);
                fma2(acc[3][0], w3, xv.x);  fma2(acc[3][1], w3, xv.y);
                fma2(acc[4][0], w4, xv.x);  fma2(acc[4][1], w4, xv.y);
                fma2(acc[5][0], w5, xv.x);  fma2(acc[5][1], w5, xv.y);
                fma2(acc[6][0], w6, xv.x);  fma2(acc[6][1], w6, xv.y);
                fma2(acc[7][0], w7, xv.x);  fma2(acc[7][1], w7, xv.y);
            }
#pragma unroll
            for (int j = 0; j < 8; j++) {
                ulonglong2 st; st.x = acc[j][0]; st.y = acc[j][1];
                *reinterpret_cast<ulonglong2*>(&t1[(r0 + j) * T1S + bc0]) = st;
            }
            __syncwarp();

            // ---- p2+p3 per row, register t2 via lane-pair shuffle ----
#pragma unroll
            for (int j = 0; j < 8; j++) {
                const int r = r0 + j;
                const int g = r >> 5, d = r & 31;
                const float* t1r = t1 + r * T1S;
                const float* w2g = w2t + g * 256;
                ull a0 = 0, a1 = 0;
#pragma unroll
                for (int b = 0; b < 16; b++) {
                    ulonglong2 tv = *reinterpret_cast<const ulonglong2*>(&t1r[b * 8 + c4]);
                    ull wd = dup2(w2g[b * 16 + e2]);
                    fma2(a0, wd, tv.x);      // t2[e2][c4, c4+1]
                    fma2(a1, wd, tv.y);      // t2[e2][c4+2, c4+3]
                }
                // lane pair {2k,2k+1} jointly holds t2[k][0..7]
                float m0, m1, m2, m3;
                unpack2(m0, m1, a0);
                unpack2(m2, m3, a1);
                float o0 = __shfl_xor_sync(0xffffffffu, m0, 1);
                float o1 = __shfl_xor_sync(0xffffffffu, m1, 1);
                float o2 = __shfl_xor_sync(0xffffffffu, m2, 1);
                float o3 = __shfl_xor_sync(0xffffffffu, m3, 1);
                float col[8];
                col[0] = loLane ? m0 : o0;  col[1] = loLane ? m1 : o1;
                col[2] = loLane ? m2 : o2;  col[3] = loLane ? m3 : o3;
                col[4] = loLane ? o0 : m0;  col[5] = loLane ? o1 : m1;
                col[6] = loLane ? o2 : m2;  col[7] = loLane ? o3 : m3;

                const float* w3g = w3s + g * 64;
                float o[4];
#pragma unroll
                for (int jj = 0; jj < 4; jj++) {
                    float4 ua = *reinterpret_cast<const float4*>(&w3g[(f0 + jj) * 8]);
                    float4 ub = *reinterpret_cast<const float4*>(&w3g[(f0 + jj) * 8 + 4]);
                    o[jj] = ua.x * col[0] + ua.y * col[1] + ua.z * col[2] + ua.w * col[3]
                          + ub.x * col[4] + ub.y * col[5] + ub.z * col[6] + ub.w * col[7];
                }
                float* outg = g_xw + (((size_t)l * 3 + g) * NB + n) * HID
                            + (d * 16 + e2) * 8 + f0;
                *reinterpret_cast<float4*>(outg) = make_float4(o[0], o[1], o[2], o[3]);
            }
        } else {
            // ---- warps 12-15: copy x[l+1] GMEM -> nxt buffer ----
            if (ll + 1 < L_PER) {
                const int tt = t - 384;     // 0..127
                const float4* src = reinterpret_cast<const float4*>(
                    x + ((size_t)n * L_STEPS + l + 1) * HID);
                float4* dst = reinterpret_cast<float4*>(nxt);
#pragma unroll
                for (int q = 0; q < 8; q++)
                    dst[q * 128 + tt] = src[q * 128 + tt];
            }
        }
        __syncthreads();   // nxt buffer visibility + t1 reuse fence
    }
}

// ---------------------------------------------------------------------------
// Stage 2: GRU recurrence (R11-exact). Cluster of 2 CTAs per sample.
// p1: 12 warps x 4 rows; one __syncthreads; p2+p3 fused in registers across
// all 16 warps (warp = dd) with shfl-pair t2 exchange; DSMEM + cluster barrier.
// ---------------------------------------------------------------------------
__global__ __launch_bounds__(512) __cluster_dims__(2, 1, 1)
void gru_kernel(
    const float* __restrict__ U1,   // (3,32,32)
    const float* __restrict__ U2,   // (3,16,16)
    const float* __restrict__ U3,   // (3,8,8)
    float* __restrict__ out)        // outs (N,L,4096) then h_last (N,4096)
{
    extern __shared__ float sm[];
    float* h0  = sm;                 // 4096
    float* h1  = h0 + 4096;          // 4096
    float* t1  = h1 + 4096;          // 48*T1S = 6144   rows r = g*16+dd
    float* u1t = t1 + 6144;          // 1536: u1t[a*48 + g*16 + dd] = U1[g, rank*16+dd, a]
    float* w2t = u1t + 1536;         // 768:  w2t[g*256 + b*16 + e] = U2[g,e,b]
    float* u3s = w2t + 768;          // 192

    const int t    = threadIdx.x;
    const int n    = blockIdx.x >> 1;
    const int rank = blockIdx.x & 1;
    const int peer = rank ^ 1;

    for (int i = t; i < 4096; i += 512) h0[i] = 0.f;
    for (int i = t; i < 1536; i += 512) {
        int g = i >> 9, rem = i & 511, dd = rem >> 5, a = rem & 31;
        u1t[a * 48 + g * 16 + dd] = U1[((g * 32) + rank * 16 + dd) * 32 + a];
    }
    for (int i = t; i < 768; i += 512) {
        int g = i >> 8, rem = i & 255, e = rem >> 4, b = rem & 15;
        w2t[g * 256 + b * 16 + e] = U2[i];
    }
    for (int i = t; i < 192; i += 512) u3s[i] = U3[i];
    __syncthreads();

    const uint32_t h0a = smem_u32(h0);
    const uint32_t h1a = smem_u32(h1);

    const int warp = t >> 5, lane = t & 31;
    const int r0  = warp * 4;
    const int bc0 = lane * 4;
    const int e2 = lane >> 1;
    const int c4 = (lane & 1) * 4;
    const int f0 = c4;
    const bool loLane = ((lane & 1) == 0);
    const int gbase = ((rank * 16 + warp) * 16 + e2) * 8 + f0;

    float* hc = h0;
    float* hn = h1;

    for (int l = 0; l < L_STEPS; l++) {
        float4 xf[3];
#pragma unroll
        for (int g = 0; g < 3; g++)
            xf[g] = *reinterpret_cast<const float4*>(
                g_xw + (((size_t)l * 3 + g) * NB + n) * HID + gbase);

        if (warp < 12) {
            ull acc2[4][2];
#pragma unroll
            for (int j = 0; j < 4; j++) { acc2[j][0] = 0; acc2[j][1] = 0; }
#pragma unroll
            for (int a = 0; a < 32; a++) {
                ulonglong2 hv = *reinterpret_cast<const ulonglong2*>(&hc[a * 128 + bc0]);
                float4 wv = *reinterpret_cast<const float4*>(&u1t[a * 48 + r0]);
                ull w0 = dup2(wv.x), w1 = dup2(wv.y), w2 = dup2(wv.z), w3 = dup2(wv.w);
                fma2(acc2[0][0], w0, hv.x);  fma2(acc2[0][1], w0, hv.y);
                fma2(acc2[1][0], w1, hv.x);  fma2(acc2[1][1], w1, hv.y);
                fma2(acc2[2][0], w2, hv.x);  fma2(acc2[2][1], w2, hv.y);
                fma2(acc2[3][0], w3, hv.x);  fma2(acc2[3][1], w3, hv.y);
            }
#pragma unroll
            for (int j = 0; j < 4; j++) {
                ulonglong2 st; st.x = acc2[j][0]; st.y = acc2[j][1];
                *reinterpret_cast<ulonglong2*>(&t1[(r0 + j) * T1S + bc0]) = st;
            }
        }
        __syncthreads();

        float hu[3][4];
#pragma unroll
        for (int g = 0; g < 3; g++) {
            const float* t1r = t1 + (g * 16 + warp) * T1S;
            const float* w2g = w2t + g * 256;
            ull a0 = 0, a1 = 0;
#pragma unroll
            for (int b = 0; b < 16; b++) {
                ulonglong2 tv = *reinterpret_cast<const ulonglong2*>(&t1r[b * 8 + c4]);
                ull wd = dup2(w2g[b * 16 + e2]);
                fma2(a0, wd, tv.x);
                fma2(a1, wd, tv.y);
            }
            float m0, m1, m2, m3;
            unpack2(m0, m1, a0);
            unpack2(m2, m3, a1);
            float o0 = __shfl_xor_sync(0xffffffffu, m0, 1);
            float o1 = __shfl_xor_sync(0xffffffffu, m1, 1);
            float o2 = __shfl_xor_sync(0xffffffffu, m2, 1);
            float o3 = __shfl_xor_sync(0xffffffffu, m3, 1);
            float col[8];
            col[0] = loLane ? m0 : o0;  col[1] = loLane ? m1 : o1;
            col[2] = loLane ? m2 : o2;  col[3] = loLane ? m3 : o3;
            col[4] = loLane ? o0 : m0;  col[5] = loLane ? o1 : m1;
            col[6] = loLane ? o2 : m2;  col[7] = loLane ? o3 : m3;

            const float* u3g = u3s + g * 64;
#pragma unroll
            for (int j = 0; j < 4; j++) {
                float4 ua = *reinterpret_cast<const float4*>(&u3g[(f0 + j) * 8]);
                float4 ub = *reinterpret_cast<const float4*>(&u3g[(f0 + j) * 8 + 4]);
                hu[g][j] = ua.x * col[0] + ua.y * col[1] + ua.z * col[2] + ua.w * col[3]
                         + ub.x * col[4] + ub.y * col[5] + ub.z * col[6] + ub.w * col[7];
            }
        }

        float4 ho = *reinterpret_cast<const float4*>(&hc[gbase]);
        float hold[4] = {ho.x, ho.y, ho.z, ho.w};
        float xz[4] = {xf[0].x, xf[0].y, xf[0].z, xf[0].w};
        float xr[4] = {xf[1].x, xf[1].y, xf[1].z, xf[1].w};
        float xh[4] = {xf[2].x, xf[2].y, xf[2].z, xf[2].w};

        float res[4];
#pragma unroll
        for (int j = 0; j < 4; j++) {
            float z  = 1.f / (1.f + __expf(-(xz[j] + hu[0][j])));
            float r  = 1.f / (1.f + __expf(-(xr[j] + hu[1][j])));
            float ax = xh[j] + r * hu[2][j];
            float e2x = __expf(2.f * ax);
            float hh = 1.f - 2.f / (e2x + 1.f);      // tanh, NaN-safe
            res[j] = z * hold[j] + (1.f - z) * hh;
        }
        float4 r4 = make_float4(res[0], res[1], res[2], res[3]);
        *reinterpret_cast<float4*>(&hn[gbase]) = r4;

        {
            uint32_t hna = (l & 1) ? h0a : h1a;
            uint32_t ra = mapa_u32(hna + (uint32_t)gbase * 4u, (uint32_t)peer);
            st_cluster_b64(ra,     pack2(res[0], res[1]));
            st_cluster_b64(ra + 8, pack2(res[2], res[3]));
        }

        asm volatile("barrier.cluster.arrive.aligned;" ::: "memory");
        *reinterpret_cast<float4*>(out + ((size_t)n * L_STEPS + l) * HID + gbase) = r4;
        asm volatile("barrier.cluster.wait.aligned;"   ::: "memory");

        float* tmp = hc; hc = hn; hn = tmp;
    }

    float* hl = out + (size_t)NB * L_STEPS * HID + (size_t)n * HID + rank * 2048;
    const float* hsrc = hc + rank * 2048;
    for (int i = t; i < 2048; i += 512) hl[i] = hsrc[i];
}

// ---------------------------------------------------------------------------
extern "C" void kernel_launch(void* const* d_in, const int* in_sizes, int n_in,
                              void* d_out, int out_size)
{
    const float* x  = (const float*)d_in[0];
    const float* W1 = (const float*)d_in[1];
    const float* W2 = (const float*)d_in[2];
    const float* W3 = (const float*)d_in[3];
    const float* U1 = (const float*)d_in[4];
    const float* U2 = (const float*)d_in[5];
    const float* U3 = (const float*)d_in[6];
    float* out = (float*)d_out;

    const int SMEM1 = (8192 + 12288 + 3072 + 768 + 192) * (int)sizeof(float);   // 98 KB
    const int SMEM2 = (4096 * 2 + 6144 + 1536 + 768 + 192) * (int)sizeof(float);

    cudaFuncSetAttribute(xw_kernel,  cudaFuncAttributeMaxDynamicSharedMemorySize, SMEM1);
    cudaFuncSetAttribute(gru_kernel, cudaFuncAttributeMaxDynamicSharedMemorySize, SMEM2);

    dim3 grid1(NB, L_STEPS / L_PER);
    xw_kernel<<<grid1, 512, SMEM1>>>(x, W1, W2, W3);
    gru_kernel<<<NB * 2, 512, SMEM2>>>(U1, U2, U3, out);
}